// round 1
// baseline (speedup 1.0000x reference)
#include <cuda_runtime.h>

// LocalCorrRatio: 4 variants x 1000 patches of 9^3 voxels, 32 Parzen bins.
// variant 0: X=y_true, Y=y_pred, shift 0
// variant 1: X=y_pred, Y=y_true, shift 0
// variant 2: X=y_true, Y=y_pred, shift 4 (roll -4 on all spatial axes)
// variant 3: X=y_pred, Y=y_true, shift 4
// result = -(sum of all 4000 patch etas) / 12000

#define NPATCH 1000
#define W3 729
#define BINS 32
#define DIM 90
#define PRETERM 961.0f   // 1/sigma^2, sigma = 1/31

__device__ float g_eta[4 * NPATCH];

__global__ __launch_bounds__(256) void eta_kernel(const float* __restrict__ yt,
                                                  const float* __restrict__ yp) {
    const int b = blockIdx.x;
    const int variant = b / NPATCH;
    const int p = b - variant * NPATCH;
    const int ph = p / 100;
    const int pw = (p / 10) % 10;
    const int pd = p % 10;
    const int shift = (variant >= 2) ? 4 : 0;
    const float* __restrict__ X = (variant & 1) ? yp : yt;
    const float* __restrict__ Y = (variant & 1) ? yt : yp;

    __shared__ float xs[W3];
    __shared__ float ys[W3];
    __shared__ float warp_w[8][BINS];
    __shared__ float warp_wx[8][BINS];
    __shared__ float red_sx[8];
    __shared__ float red_sx2[8];
    __shared__ float s_mean, s_var;

    const int tid = threadIdx.x;
    const int warp = tid >> 5;
    const int lane = tid & 31;

    // ---- Phase A: load patch into shared, accumulate sum_x / sum_x2 ----
    float sx = 0.0f, sx2 = 0.0f;
    for (int idx = tid; idx < W3; idx += 256) {
        int i = idx / 81;
        int r = idx - i * 81;
        int j = r / 9;
        int k = r - j * 9;
        int gi = ph * 9 + i + shift; if (gi >= DIM) gi -= DIM;
        int gj = pw * 9 + j + shift; if (gj >= DIM) gj -= DIM;
        int gk = pd * 9 + k + shift; if (gk >= DIM) gk -= DIM;
        int g = (gi * DIM + gj) * DIM + gk;
        float xv = X[g];
        float yv = Y[g];
        xs[idx] = xv;
        ys[idx] = yv;
        sx += xv;
        sx2 = fmaf(xv, xv, sx2);
    }
    #pragma unroll
    for (int o = 16; o; o >>= 1) {
        sx  += __shfl_xor_sync(0xffffffffu, sx, o);
        sx2 += __shfl_xor_sync(0xffffffffu, sx2, o);
    }
    if (lane == 0) { red_sx[warp] = sx; red_sx2[warp] = sx2; }
    __syncthreads();

    if (tid == 0) {
        float tsx = 0.0f, tsx2 = 0.0f;
        #pragma unroll
        for (int w = 0; w < 8; w++) { tsx += red_sx[w]; tsx2 += red_sx2[w]; }
        float mean = tsx * (1.0f / (float)W3);
        // unbiased variance (ddof=1)
        float var = (tsx2 - tsx * tsx * (1.0f / (float)W3)) * (1.0f / (float)(W3 - 1));
        s_mean = mean;
        s_var = var;
    }

    // ---- Phase B: lane = bin; each warp handles a strided slice of voxels ----
    const float c = (float)lane * (1.0f / 31.0f);
    float Sw = 0.0f, Swx = 0.0f;
    for (int v = warp; v < W3; v += 8) {
        float yv = ys[v];
        float xv = xs[v];
        float d = yv - c;
        float w = __expf(-PRETERM * d * d);
        Sw += w;
        Swx = fmaf(w, xv, Swx);
    }
    warp_w[warp][lane] = Sw;
    warp_wx[warp][lane] = Swx;
    __syncthreads();

    // ---- Phase C: warp 0 finalizes eta ----
    if (warp == 0) {
        float SwT = 0.0f, SwxT = 0.0f;
        #pragma unroll
        for (int w = 0; w < 8; w++) {
            SwT  += warp_w[w][lane];
            SwxT += warp_wx[w][lane];
        }
        float mean = s_mean;
        float var = s_var;
        float mi = SwxT / (SwT + 1e-5f);
        float dm = mi - mean;
        float num = SwT * dm * dm;
        float den = SwT;
        #pragma unroll
        for (int o = 16; o; o >>= 1) {
            num += __shfl_xor_sync(0xffffffffu, num, o);
            den += __shfl_xor_sync(0xffffffffu, den, o);
        }
        if (lane == 0) {
            g_eta[b] = (num / den) / (var + 1e-5f);
        }
    }
}

__global__ __launch_bounds__(256) void reduce_kernel(float* __restrict__ out) {
    __shared__ double sh[256];
    int tid = threadIdx.x;
    double s = 0.0;
    for (int i = tid; i < 4 * NPATCH; i += 256) s += (double)g_eta[i];
    sh[tid] = s;
    __syncthreads();
    #pragma unroll
    for (int o = 128; o; o >>= 1) {
        if (tid < o) sh[tid] += sh[tid + o];
        __syncthreads();
    }
    if (tid == 0) out[0] = (float)(-sh[0] / 12000.0);
}

extern "C" void kernel_launch(void* const* d_in, const int* in_sizes, int n_in,
                              void* d_out, int out_size) {
    const float* y_true = (const float*)d_in[0];
    const float* y_pred = (const float*)d_in[1];
    float* out = (float*)d_out;
    eta_kernel<<<4 * NPATCH, 256>>>(y_true, y_pred);
    reduce_kernel<<<1, 256>>>(out);
}

// round 2
// speedup vs baseline: 1.1979x; 1.1979x over previous
#include <cuda_runtime.h>

// LocalCorrRatio fused kernel.
// 2000 blocks: pair-index q = vp*1000 + p, vp=0 -> shift 0 (variants 0,1),
// vp=1 -> shift 4 (variants 2,3). Each block computes BOTH swap-direction etas
// for its patch (they share the loaded data). Last block reduces all 4000 etas.

#define NPATCH 1000
#define W3 729
#define W3PAD 736        // 8 warps x 92 voxels
#define BINS 32
#define DIM 90
#define PRETERM 961.0f

__device__ float g_eta[4 * NPATCH];
__device__ unsigned int g_count = 0;

__global__ __launch_bounds__(256) void lcr_kernel(const float* __restrict__ yt,
                                                  const float* __restrict__ yp,
                                                  float* __restrict__ out) {
    const int q = blockIdx.x;
    const int vp = q / NPATCH;          // 0: shift 0, 1: shift 4
    const int p = q - vp * NPATCH;
    const int ph = p / 100;
    const int pw = (p / 10) % 10;
    const int pd = p % 10;
    const int shift = vp ? 4 : 0;

    __shared__ __align__(16) float2 sv[W3PAD];   // {true, pred} interleaved
    __shared__ float accAw[8][BINS], accAx[8][BINS];
    __shared__ float accBw[8][BINS], accBx[8][BINS];
    __shared__ float red[4][8];
    __shared__ float s_meanT, s_varT, s_meanP, s_varP;
    __shared__ unsigned int s_islast;

    const int tid = threadIdx.x;
    const int warp = tid >> 5;
    const int lane = tid & 31;

    // ---- Phase A: load patch, stats for both true and pred ----
    if (tid < W3PAD - W3) sv[W3 + tid] = make_float2(4.0f, 4.0f);  // w == 0 padding

    float st = 0.0f, st2 = 0.0f, sp = 0.0f, sp2 = 0.0f;
    for (int idx = tid; idx < W3; idx += 256) {
        int i = idx / 81;
        int r = idx - i * 81;
        int j = r / 9;
        int k = r - j * 9;
        int gi = ph * 9 + i + shift; if (gi >= DIM) gi -= DIM;
        int gj = pw * 9 + j + shift; if (gj >= DIM) gj -= DIM;
        int gk = pd * 9 + k + shift; if (gk >= DIM) gk -= DIM;
        int g = (gi * DIM + gj) * DIM + gk;
        float tv = yt[g];
        float pv = yp[g];
        sv[idx] = make_float2(tv, pv);
        st += tv;  st2 = fmaf(tv, tv, st2);
        sp += pv;  sp2 = fmaf(pv, pv, sp2);
    }
    #pragma unroll
    for (int o = 16; o; o >>= 1) {
        st  += __shfl_xor_sync(0xffffffffu, st,  o);
        st2 += __shfl_xor_sync(0xffffffffu, st2, o);
        sp  += __shfl_xor_sync(0xffffffffu, sp,  o);
        sp2 += __shfl_xor_sync(0xffffffffu, sp2, o);
    }
    if (lane == 0) {
        red[0][warp] = st; red[1][warp] = st2;
        red[2][warp] = sp; red[3][warp] = sp2;
    }
    __syncthreads();
    if (tid == 0) {
        float a = 0, b = 0, c = 0, d = 0;
        #pragma unroll
        for (int w = 0; w < 8; w++) { a += red[0][w]; b += red[1][w]; c += red[2][w]; d += red[3][w]; }
        s_meanT = a * (1.0f / (float)W3);
        s_varT  = (b - a * a * (1.0f / (float)W3)) * (1.0f / (float)(W3 - 1));
        s_meanP = c * (1.0f / (float)W3);
        s_varP  = (d - c * c * (1.0f / (float)W3)) * (1.0f / (float)(W3 - 1));
    }
    __syncthreads();

    // ---- Phase B: lane = bin; warp w handles voxels [92w, 92w+92) ----
    const float cb = (float)lane * (1.0f / 31.0f);
    const float4* s4 = (const float4*)sv;
    int base4 = warp * 46;
    // A: Y = pred, X = true.  B: Y = true, X = pred.
    float SwA = 0.0f, SxA = 0.0f, SwB = 0.0f, SxB = 0.0f;
    #pragma unroll 2
    for (int i = 0; i < 46; i++) {
        float4 v = s4[base4 + i];
        // voxel 0: t=v.x p=v.y ; voxel 1: t=v.z p=v.w
        float dA0 = v.y - cb;
        float dB0 = v.x - cb;
        float dA1 = v.w - cb;
        float dB1 = v.z - cb;
        float wA0 = __expf(-PRETERM * dA0 * dA0);
        float wB0 = __expf(-PRETERM * dB0 * dB0);
        float wA1 = __expf(-PRETERM * dA1 * dA1);
        float wB1 = __expf(-PRETERM * dB1 * dB1);
        SwA += wA0; SxA = fmaf(wA0, v.x, SxA);
        SwB += wB0; SxB = fmaf(wB0, v.y, SxB);
        SwA += wA1; SxA = fmaf(wA1, v.z, SxA);
        SwB += wB1; SxB = fmaf(wB1, v.w, SxB);
    }
    accAw[warp][lane] = SwA; accAx[warp][lane] = SxA;
    accBw[warp][lane] = SwB; accBx[warp][lane] = SxB;
    __syncthreads();

    // ---- Phase C: warp 0 -> eta A, warp 1 -> eta B ----
    if (warp < 2) {
        float Sw = 0.0f, Sx = 0.0f;
        if (warp == 0) {
            #pragma unroll
            for (int w = 0; w < 8; w++) { Sw += accAw[w][lane]; Sx += accAx[w][lane]; }
        } else {
            #pragma unroll
            for (int w = 0; w < 8; w++) { Sw += accBw[w][lane]; Sx += accBx[w][lane]; }
        }
        float mean = (warp == 0) ? s_meanT : s_meanP;
        float var  = (warp == 0) ? s_varT  : s_varP;
        float mi = Sx / (Sw + 1e-5f);
        float dm = mi - mean;
        float num = Sw * dm * dm;
        float den = Sw;
        #pragma unroll
        for (int o = 16; o; o >>= 1) {
            num += __shfl_xor_sync(0xffffffffu, num, o);
            den += __shfl_xor_sync(0xffffffffu, den, o);
        }
        if (lane == 0) {
            // variant index: vp*2 + warp  (0:T,P s0 | 1:P,T s0 | 2:T,P s4 | 3:P,T s4)
            g_eta[(vp * 2 + warp) * NPATCH + p] = (num / den) / (var + 1e-5f);
        }
    }
    __syncthreads();

    // ---- Last block reduces all 4000 etas ----
    if (tid == 0) {
        __threadfence();
        unsigned int old = atomicAdd(&g_count, 1u);
        s_islast = (old == 2 * NPATCH - 1) ? 1u : 0u;
    }
    __syncthreads();
    if (s_islast) {
        __shared__ double sh[256];
        double s = 0.0;
        for (int i = tid; i < 4 * NPATCH; i += 256) s += (double)g_eta[i];
        sh[tid] = s;
        __syncthreads();
        #pragma unroll
        for (int o = 128; o; o >>= 1) {
            if (tid < o) sh[tid] += sh[tid + o];
            __syncthreads();
        }
        if (tid == 0) {
            out[0] = (float)(-sh[0] / 12000.0);
            g_count = 0;   // reset for next graph replay
        }
    }
}

extern "C" void kernel_launch(void* const* d_in, const int* in_sizes, int n_in,
                              void* d_out, int out_size) {
    const float* y_true = (const float*)d_in[0];
    const float* y_pred = (const float*)d_in[1];
    float* out = (float*)d_out;
    lcr_kernel<<<2 * NPATCH, 256>>>(y_true, y_pred, out);
}

// round 3
// speedup vs baseline: 1.3753x; 1.1481x over previous
#include <cuda_runtime.h>

// LocalCorrRatio fused kernel, packed-f32x2 inner loop.
// 2000 blocks: q = vp*1000 + p; vp=0 -> shift 0 (variants 0,1), vp=1 -> shift 4.
// Each block computes both swap-direction etas for its patch. Last block reduces.

#define NPATCH 1000
#define W3 729
#define W3PAD 736        // 8 warps x 92 voxels
#define BINS 32
#define DIM 90
#define KEXP (-1386.4299343f)   // -961 * log2(e)

typedef unsigned long long ull;

__device__ float g_eta[4 * NPATCH];
__device__ unsigned int g_count = 0;

__device__ __forceinline__ ull pk2(float a, float b) {
    ull r; asm("mov.b64 %0, {%1, %2};" : "=l"(r) : "f"(a), "f"(b)); return r;
}
__device__ __forceinline__ float plo(ull v) { return __uint_as_float((unsigned)(v & 0xffffffffull)); }
__device__ __forceinline__ float phi(ull v) { return __uint_as_float((unsigned)(v >> 32)); }

__device__ __forceinline__ ull addx2(ull a, ull b) {
    ull r; asm("add.rn.f32x2 %0, %1, %2;" : "=l"(r) : "l"(a), "l"(b)); return r;
}
__device__ __forceinline__ ull fmax2(ull a, ull b, ull c) {
    ull r; asm("fma.rn.f32x2 %0, %1, %2, %3;" : "=l"(r) : "l"(a), "l"(b), "l"(c)); return r;
}
// w = exp2(K * (y - c)^2) for both packed lanes
__device__ __forceinline__ ull expw_pair(ull y, ull negc, ull K) {
    ull r;
    asm("{\n\t"
        ".reg .b64 d, t;\n\t"
        ".reg .f32 lo, hi;\n\t"
        "add.rn.f32x2 d, %1, %2;\n\t"
        "mul.rn.f32x2 d, d, d;\n\t"
        "mul.rn.f32x2 t, d, %3;\n\t"
        "mov.b64 {lo, hi}, t;\n\t"
        "ex2.approx.f32 lo, lo;\n\t"
        "ex2.approx.f32 hi, hi;\n\t"
        "mov.b64 %0, {lo, hi};\n\t"
        "}" : "=l"(r) : "l"(y), "l"(negc), "l"(K));
    return r;
}

__global__ __launch_bounds__(256) void lcr_kernel(const float* __restrict__ yt,
                                                  const float* __restrict__ yp,
                                                  float* __restrict__ out) {
    const int q = blockIdx.x;
    const int vp = q / NPATCH;
    const int p = q - vp * NPATCH;
    const int ph = p / 100;
    const int pw = (p / 10) % 10;
    const int pd = p % 10;
    const int shift = vp ? 4 : 0;

    __shared__ __align__(16) float ts[W3PAD];   // y_true
    __shared__ __align__(16) float ps[W3PAD];   // y_pred
    __shared__ float accAw[8][BINS], accAx[8][BINS];
    __shared__ float accBw[8][BINS], accBx[8][BINS];
    __shared__ float red[4][8];
    __shared__ float s_meanT, s_varT, s_meanP, s_varP;
    __shared__ unsigned int s_islast;

    const int tid = threadIdx.x;
    const int warp = tid >> 5;
    const int lane = tid & 31;

    // ---- Phase A: load patch, stats for both images ----
    if (tid < W3PAD - W3) { ts[W3 + tid] = 4.0f; ps[W3 + tid] = 4.0f; }  // w==0 pad

    float st = 0.0f, st2 = 0.0f, sp = 0.0f, sp2 = 0.0f;
    for (int idx = tid; idx < W3; idx += 256) {
        int i = idx / 81;
        int r = idx - i * 81;
        int j = r / 9;
        int k = r - j * 9;
        int gi = ph * 9 + i + shift; if (gi >= DIM) gi -= DIM;
        int gj = pw * 9 + j + shift; if (gj >= DIM) gj -= DIM;
        int gk = pd * 9 + k + shift; if (gk >= DIM) gk -= DIM;
        int g = (gi * DIM + gj) * DIM + gk;
        float tv = yt[g];
        float pv = yp[g];
        ts[idx] = tv;
        ps[idx] = pv;
        st += tv;  st2 = fmaf(tv, tv, st2);
        sp += pv;  sp2 = fmaf(pv, pv, sp2);
    }
    #pragma unroll
    for (int o = 16; o; o >>= 1) {
        st  += __shfl_xor_sync(0xffffffffu, st,  o);
        st2 += __shfl_xor_sync(0xffffffffu, st2, o);
        sp  += __shfl_xor_sync(0xffffffffu, sp,  o);
        sp2 += __shfl_xor_sync(0xffffffffu, sp2, o);
    }
    if (lane == 0) {
        red[0][warp] = st; red[1][warp] = st2;
        red[2][warp] = sp; red[3][warp] = sp2;
    }
    __syncthreads();
    if (tid == 0) {
        float a = 0, b = 0, c = 0, d = 0;
        #pragma unroll
        for (int w = 0; w < 8; w++) { a += red[0][w]; b += red[1][w]; c += red[2][w]; d += red[3][w]; }
        s_meanT = a * (1.0f / (float)W3);
        s_varT  = (b - a * a * (1.0f / (float)W3)) * (1.0f / (float)(W3 - 1));
        s_meanP = c * (1.0f / (float)W3);
        s_varP  = (d - c * c * (1.0f / (float)W3)) * (1.0f / (float)(W3 - 1));
    }
    __syncthreads();

    // ---- Phase B: lane = bin; warp w handles voxels [92w, 92w+92) ----
    const float cb = (float)lane * (1.0f / 31.0f);
    const ull negc = pk2(-cb, -cb);
    const ull K    = pk2(KEXP, KEXP);

    const ulonglong2* tq4 = (const ulonglong2*)ts;
    const ulonglong2* pq4 = (const ulonglong2*)ps;
    const int base = warp * 23;   // 23 ulonglong2 = 92 floats per warp

    // A: Y=pred, X=true.  B: Y=true, X=pred.  Two accumulator chains each.
    ull SwA0 = 0, SwA1 = 0, SxA0 = 0, SxA1 = 0;
    ull SwB0 = 0, SwB1 = 0, SxB0 = 0, SxB1 = 0;
    #pragma unroll 4
    for (int i = 0; i < 23; i++) {
        ulonglong2 tq = tq4[base + i];   // {t0,t1},{t2,t3}
        ulonglong2 pq = pq4[base + i];   // {p0,p1},{p2,p3}
        ull wA0 = expw_pair(pq.x, negc, K);
        ull wA1 = expw_pair(pq.y, negc, K);
        ull wB0 = expw_pair(tq.x, negc, K);
        ull wB1 = expw_pair(tq.y, negc, K);
        SwA0 = addx2(SwA0, wA0);  SxA0 = fmax2(wA0, tq.x, SxA0);
        SwA1 = addx2(SwA1, wA1);  SxA1 = fmax2(wA1, tq.y, SxA1);
        SwB0 = addx2(SwB0, wB0);  SxB0 = fmax2(wB0, pq.x, SxB0);
        SwB1 = addx2(SwB1, wB1);  SxB1 = fmax2(wB1, pq.y, SxB1);
    }
    ull SwA = addx2(SwA0, SwA1), SxA = addx2(SxA0, SxA1);
    ull SwB = addx2(SwB0, SwB1), SxB = addx2(SxB0, SxB1);
    accAw[warp][lane] = plo(SwA) + phi(SwA);
    accAx[warp][lane] = plo(SxA) + phi(SxA);
    accBw[warp][lane] = plo(SwB) + phi(SwB);
    accBx[warp][lane] = plo(SxB) + phi(SxB);
    __syncthreads();

    // ---- Phase C: warp 0 -> eta A, warp 1 -> eta B ----
    if (warp < 2) {
        float Sw = 0.0f, Sx = 0.0f;
        if (warp == 0) {
            #pragma unroll
            for (int w = 0; w < 8; w++) { Sw += accAw[w][lane]; Sx += accAx[w][lane]; }
        } else {
            #pragma unroll
            for (int w = 0; w < 8; w++) { Sw += accBw[w][lane]; Sx += accBx[w][lane]; }
        }
        float mean = (warp == 0) ? s_meanT : s_meanP;
        float var  = (warp == 0) ? s_varT  : s_varP;
        float mi = Sx / (Sw + 1e-5f);
        float dm = mi - mean;
        float num = Sw * dm * dm;
        float den = Sw;
        #pragma unroll
        for (int o = 16; o; o >>= 1) {
            num += __shfl_xor_sync(0xffffffffu, num, o);
            den += __shfl_xor_sync(0xffffffffu, den, o);
        }
        if (lane == 0) {
            g_eta[(vp * 2 + warp) * NPATCH + p] = (num / den) / (var + 1e-5f);
        }
    }
    __syncthreads();

    // ---- Last block reduces all 4000 etas ----
    if (tid == 0) {
        __threadfence();
        unsigned int old = atomicAdd(&g_count, 1u);
        s_islast = (old == 2 * NPATCH - 1) ? 1u : 0u;
    }
    __syncthreads();
    if (s_islast) {
        __shared__ double sh[256];
        double s = 0.0;
        for (int i = tid; i < 4 * NPATCH; i += 256) s += (double)g_eta[i];
        sh[tid] = s;
        __syncthreads();
        #pragma unroll
        for (int o = 128; o; o >>= 1) {
            if (tid < o) sh[tid] += sh[tid + o];
            __syncthreads();
        }
        if (tid == 0) {
            out[0] = (float)(-sh[0] / 12000.0);
            g_count = 0;
        }
    }
}

extern "C" void kernel_launch(void* const* d_in, const int* in_sizes, int n_in,
                              void* d_out, int out_size) {
    const float* y_true = (const float*)d_in[0];
    const float* y_pred = (const float*)d_in[1];
    float* out = (float*)d_out;
    lcr_kernel<<<2 * NPATCH, 256>>>(y_true, y_pred, out);
}